// round 9
// baseline (speedup 1.0000x reference)
#include <cuda_runtime.h>
#include <cstdint>

// VanillaRNN B=128,S=2048,E=256,H=512,V=128 fp32 — persistent kernel v5.
// Round-8: warp-autonomous steps.
//  - K-reduction via in-warp recursive-halving shuffle (no partials SMEM,
//    no reduce syncs). Lane l of each warp finalizes (row l>>2, colpair l&3).
//  - per-warp red.release arrivals (256 per row-group step).
//  - warp-pair h staging with 64-thread named barrier; zero CTA-wide
//    __syncthreads in the step loop.
//  - xw table (emb@Wx+bx+bh, 128 tokens x 16 cols) computed in prologue
//    into SMEM; finalize reads it via LDS.

#define Bb   128
#define Ss   2048
#define Vv   128
#define Ee   256
#define Hh   512
#define NBLK 128
#define NTHR 256

// SMEM offsets (floats)
#define OFF_SH   0                      // h tile: 32 x 512 (unit-swizzled)
#define OFF_WH   16384                  // WhT k-major: 512 x 16 (swizzled)
#define OFF_WF   24576                  // WfcT: 4 x 512 (k-unit swizzled)
#define OFF_XW   26624                  // xw slice: 128 tokens x 16 cols
#define SMEM_FLOATS 28672
#define SMEM_BYTES  (SMEM_FLOATS * 4)

__device__ float g_h[2][Bb * Hh];       // double-buffered hidden state
__device__ int   g_bar4[4 * 32];        // per-row-group counters, 128B apart

static __device__ __forceinline__ float2 ffma2(float2 a, float2 b, float2 c) {
    union { float2 f; unsigned long long u; } A, B2, C;
    A.f = a; B2.f = b; C.f = c;
    asm("fma.rn.f32x2 %0, %1, %2, %0;" : "+l"(C.u) : "l"(A.u), "l"(B2.u));
    return C.f;
}
static __device__ __forceinline__ int swz_h (int u) { return u ^ ((u >> 3) & 7); }
static __device__ __forceinline__ int swz_wh(int u) { return u ^ ((u >> 6) & 7); }

// one recursive-halving butterfly round over float2 array v[m]:
// keep half selected by (lane & s), add partner's matching half.
#define BFLY2(v, m, s) {                                                  \
    const int  half_ = (m) >> 1;                                          \
    const bool up_ = (lane & (s)) != 0;                                   \
    _Pragma("unroll")                                                     \
    for (int i_ = 0; i_ < half_; ++i_) {                                  \
        float2 d_ = up_ ? v[i_] : v[i_ + half_];                          \
        float2 o_;                                                        \
        o_.x = __shfl_xor_sync(0xffffffffu, d_.x, (s));                   \
        o_.y = __shfl_xor_sync(0xffffffffu, d_.y, (s));                   \
        float2 k_ = up_ ? v[i_ + half_] : v[i_];                          \
        v[i_].x = k_.x + o_.x;                                            \
        v[i_].y = k_.y + o_.y;                                            \
    } }

__global__ void rnn_init_kernel() {
    int idx = blockIdx.x * blockDim.x + threadIdx.x;
    for (int i = idx; i < Bb * Hh; i += gridDim.x * blockDim.x)
        g_h[1][i] = 0.0f;               // h_{-1} = 0 (read at t=0)
    if (idx < 4 * 32) g_bar4[idx] = 0;
}

__global__ void __launch_bounds__(NTHR, 1)
rnn_persistent(const int*   __restrict__ x,
               const float* __restrict__ emb,
               const float* __restrict__ Wx,
               const float* __restrict__ bx,
               const float* __restrict__ Wh,
               const float* __restrict__ bh,
               const float* __restrict__ Wfc,
               const float* __restrict__ bfc,
               float* __restrict__ out)
{
    extern __shared__ float sm[];
    const int tid  = threadIdx.x;
    const int bidx = blockIdx.x;
    const int rgc  = bidx >> 5;          // row-group 0..3 (32 B-rows)
    const int R0   = rgc << 5;
    const int cg   = bidx & 31;
    const int C0   = cg << 4;            // 16 H-cols
    const int VC0  = cg << 2;            // 4 V-cols
    const int lane = tid & 31;           // = k-slice (16 k's each)
    const int ks   = lane;
    const int rc   = tid >> 5;
    const int rowg = rc >> 1;            // rows rowg*8 .. +7
    const int colg = rc & 1;             // cols colg*8 .. +7 (of 16)
    int* bar = &g_bar4[rgc * 32];
    // finalize mapping (butterfly output): row fr, col pair fc
    const int fr = lane >> 2;            // 0..7 within rowg block
    const int fc = 2 * (lane & 3);       // 0,2,4,6 within colg 8-col block

    uint32_t smem_u32;
    asm("{ .reg .u64 t0; cvta.to.shared.u64 t0, %1; cvt.u32.u64 %0, t0; }"
        : "=r"(smem_u32) : "l"(sm));

    // ---- prologue: Wh (k-major swizzled), Wfc slice, xw table ----------
    for (int idx = tid; idx < Hh * 16; idx += NTHR) {
        const int k = idx >> 4, c = idx & 15;
        const int u = idx >> 2, l = idx & 3;
        sm[OFF_WH + swz_wh(u) * 4 + l] = Wh[k * Hh + C0 + c];
    }
    for (int idx = tid; idx < 4 * Hh; idx += NTHR) {
        const int c = idx >> 9, k = idx & 511;
        const int u = k >> 2,  l = k & 3;
        sm[OFF_WF + (c << 9) + swz_h(u) * 4 + l] = Wfc[k * Vv + VC0 + c];
    }
    {   // xw[v][0..15] = emb[v] @ Wx[:, C0..C0+16) + bx + bh
        const int v  = tid >> 1;
        const int cb = (tid & 1) * 8;
        float acc[8];
#pragma unroll
        for (int i = 0; i < 8; ++i) acc[i] = 0.f;
        const float* er = emb + v * Ee;
#pragma unroll 4
        for (int e = 0; e < Ee; ++e) {
            const float  ev = __ldg(er + e);
            const float4 w0 = __ldg((const float4*)(Wx + e * Hh + C0 + cb));
            const float4 w1 = __ldg((const float4*)(Wx + e * Hh + C0 + cb + 4));
            acc[0] = fmaf(ev, w0.x, acc[0]); acc[1] = fmaf(ev, w0.y, acc[1]);
            acc[2] = fmaf(ev, w0.z, acc[2]); acc[3] = fmaf(ev, w0.w, acc[3]);
            acc[4] = fmaf(ev, w1.x, acc[4]); acc[5] = fmaf(ev, w1.y, acc[5]);
            acc[6] = fmaf(ev, w1.z, acc[6]); acc[7] = fmaf(ev, w1.w, acc[7]);
        }
#pragma unroll
        for (int i = 0; i < 8; ++i)
            sm[OFF_XW + v * 16 + cb + i] =
                acc[i] + __ldg(bx + C0 + cb + i) + __ldg(bh + C0 + cb + i);
    }
    const float2 bfcv = *(const float2*)(bfc + VC0 + colg * 2);
    __syncthreads();                      // the only CTA-wide sync

    const float4* wh4 = (const float4*)(sm + OFF_WH);
    const int hrow0 = rowg * 8;           // this warp's 8 tile rows

    for (int t = 0; t <= Ss; ++t) {
        // ---- (A) all-lane acquire poll on the row-group counter --------
        if (t > 0) {
            const int target = t << 8;    // 256 arrivals per step
            int v;
            do {
                asm volatile("ld.acquire.gpu.global.b32 %0, [%1];"
                             : "=r"(v) : "l"(bar) : "memory");
            } while (v - target < 0);
        }
        // ---- token for this lane's finalize row (early issue) ----------
        int tk = 0;
        if (t < Ss) tk = __ldg(x + (R0 + hrow0 + fr) * Ss + t);

        // ---- (B) stage this warp's 4 h rows, pair-sync via named bar ---
        const float* hsrc = g_h[(t + 1) & 1];
        const int rb = hrow0 + colg * 4;  // 4 rows this warp stages
#pragma unroll
        for (int q = 0; q < 16; ++q) {
            const int g2 = lane + (q << 5);       // 0..511
            const int rl = rb + (g2 >> 7);
            const int u  = g2 & 127;
            const uint32_t sa = smem_u32 +
                (uint32_t)((OFF_SH + (rl << 9) + swz_h(u) * 4) * 4);
            const float4* ga = ((const float4*)(hsrc + ((R0 + rl) << 9))) + u;
            asm volatile("cp.async.cg.shared.global [%0], [%1], 16;"
                         :: "r"(sa), "l"(ga));
        }
        asm volatile("cp.async.commit_group;");
        asm volatile("cp.async.wait_group 0;");
        asm volatile("bar.sync %0, %1;" :: "r"(1 + rowg), "r"(64) : "memory");

        float2 accV[8];
#pragma unroll
        for (int r = 0; r < 8; ++r) accV[r] = make_float2(0.f, 0.f);

        if (t < Ss) {
            float2 accR[32];              // [r*4+q] -> cols (2q, 2q+1)
#pragma unroll
            for (int p = 0; p < 32; ++p) accR[p] = make_float2(0.f, 0.f);

            // ---- (D) recurrence (16 k's) fused with V-proj of h(t-1) ---
#pragma unroll
            for (int m = 0; m < 4; ++m) {
                const int um = swz_h(ks * 4 + m);
                float4 h4[8];
#pragma unroll
                for (int r = 0; r < 8; ++r)
                    h4[r] = *(const float4*)(sm + OFF_SH
                              + ((hrow0 + r) << 9) + um * 4);
                const float4 wfa = *(const float4*)(sm + OFF_WF
                              + ((colg * 2 + 0) << 9) + um * 4);
                const float4 wfb = *(const float4*)(sm + OFF_WF
                              + ((colg * 2 + 1) << 9) + um * 4);
#pragma unroll
                for (int ki = 0; ki < 4; ++ki) {
                    const int u  = ks * 64 + (m * 4 + ki) * 4 + colg * 2;
                    const float4 wa = wh4[u ^ (ks & 7)];
                    const float4 wb = wh4[(u + 1) ^ (ks & 7)];
                    const float2 wv = make_float2(((const float*)&wfa)[ki],
                                                  ((const float*)&wfb)[ki]);
#pragma unroll
                    for (int r = 0; r < 8; ++r) {
                        const float hv = ((const float*)&h4[r])[ki];
                        const float2 hh = make_float2(hv, hv);
                        accR[r*4+0] = ffma2(hh, make_float2(wa.x, wa.y), accR[r*4+0]);
                        accR[r*4+1] = ffma2(hh, make_float2(wa.z, wa.w), accR[r*4+1]);
                        accR[r*4+2] = ffma2(hh, make_float2(wb.x, wb.y), accR[r*4+2]);
                        accR[r*4+3] = ffma2(hh, make_float2(wb.z, wb.w), accR[r*4+3]);
                        accV[r]     = ffma2(hh, wv, accV[r]);
                    }
                }
            }

            // ---- (E) in-warp K reduce -> finalize -> publish -----------
            BFLY2(accR, 32, 16);
            BFLY2(accR, 16,  8);
            BFLY2(accR,  8,  4);
            BFLY2(accR,  4,  2);
            BFLY2(accR,  2,  1);
            // lane holds output (row hrow0+fr, cols C0+colg*8+fc..+1)
            const float2 xa = *(const float2*)(sm + OFF_XW + tk * 16
                                               + colg * 8 + fc);
            float2 s;
            s.x = tanhf(accR[0].x + xa.x);
            s.y = tanhf(accR[0].y + xa.y);
            *(float2*)(&g_h[t & 1][((R0 + hrow0 + fr) << 9)
                                   + C0 + colg * 8 + fc]) = s;
            if (lane == 0)
                asm volatile("red.release.gpu.global.add.s32 [%0], %1;"
                             :: "l"(bar), "r"(1) : "memory");
        } else {
            // t == Ss: output projection of h(Ss-1) only
#pragma unroll
            for (int m = 0; m < 4; ++m) {
                const int um = swz_h(ks * 4 + m);
                const float4 wfa = *(const float4*)(sm + OFF_WF
                              + ((colg * 2 + 0) << 9) + um * 4);
                const float4 wfb = *(const float4*)(sm + OFF_WF
                              + ((colg * 2 + 1) << 9) + um * 4);
#pragma unroll
                for (int r = 0; r < 8; ++r) {
                    const float4 h4 = *(const float4*)(sm + OFF_SH
                              + ((hrow0 + r) << 9) + um * 4);
#pragma unroll
                    for (int ki = 0; ki < 4; ++ki) {
                        const float hv = ((const float*)&h4)[ki];
                        const float2 wv = make_float2(((const float*)&wfa)[ki],
                                                      ((const float*)&wfb)[ki]);
                        accV[r] = ffma2(make_float2(hv, hv), wv, accV[r]);
                    }
                }
            }
        }

        // ---- (F) out(t-1): in-warp reduce, off inter-CTA path ----------
        if (t > 0) {
            BFLY2(accV, 8, 16);
            BFLY2(accV, 4,  8);
            BFLY2(accV, 2,  4);
            // accV[0] reduced over lanes^{16,8,4}; finish all 32 lanes:
            accV[0].x += __shfl_xor_sync(0xffffffffu, accV[0].x, 2);
            accV[0].y += __shfl_xor_sync(0xffffffffu, accV[0].y, 2);
            accV[0].x += __shfl_xor_sync(0xffffffffu, accV[0].x, 1);
            accV[0].y += __shfl_xor_sync(0xffffffffu, accV[0].y, 1);
            if ((lane & 3) == 0) {
                float2 o = make_float2(accV[0].x + bfcv.x, accV[0].y + bfcv.y);
                *(float2*)(out + (long)(R0 + hrow0 + fr) * (Ss * Vv)
                           + (long)(t - 1) * Vv + VC0 + colg * 2) = o;
            }
        }
    }
}

extern "C" void kernel_launch(void* const* d_in, const int* in_sizes, int n_in,
                              void* d_out, int out_size) {
    const int*   x   = (const int*)  d_in[0];
    const float* emb = (const float*)d_in[1];
    const float* Wx  = (const float*)d_in[2];
    const float* bx  = (const float*)d_in[3];
    const float* Wh  = (const float*)d_in[4];
    const float* bh  = (const float*)d_in[5];
    const float* Wfc = (const float*)d_in[6];
    const float* bfc = (const float*)d_in[7];
    float* out = (float*)d_out;

    cudaFuncSetAttribute(rnn_persistent,
                         cudaFuncAttributeMaxDynamicSharedMemorySize, SMEM_BYTES);

    rnn_init_kernel<<<64, 256>>>();
    rnn_persistent<<<NBLK, NTHR, SMEM_BYTES>>>(x, emb, Wx, bx, Wh, bh,
                                               Wfc, bfc, out);
}

// round 10
// speedup vs baseline: 1.0887x; 1.0887x over previous
#include <cuda_runtime.h>
#include <cstdint>

// VanillaRNN B=128,S=2048,E=256,H=512,V=128 fp32 — persistent kernel v6.
// Round-9: 16x32 tiling (8 row-groups x 16 CTAs), barrier domain 16,
// 32KB h staging split into two cp.async halves overlapped with compute,
// k-chunk remap (k = m*128 + ks*4 + ki) -> near-swizzle-free addressing,
// v4 SMEM reduce for h (butterfly only for tiny V out-path), xw global table.

#define Bb   128
#define Ss   2048
#define Vv   128
#define Ee   256
#define Hh   512
#define NBLK 128
#define NTHR 256

#define RR_STRIDE 516        // Δbank 4 per k-slice row -> conflict-free

// SMEM offsets (floats)
#define OFF_SH   0                       // h tile: 16 x 512 (plain layout)
#define OFF_WH   8192                    // Wh slice: 512 x 32 (unit-XOR swz)
#define OFF_WF   24576                   // Wfc slice: 8 cols x 512 k
#define OFF_RR   28672                   // rec partials: 32 x 516
#define SMEM_FLOATS (OFF_RR + 32 * RR_STRIDE)
#define SMEM_BYTES  (SMEM_FLOATS * 4)

__device__ float g_h[2][Bb * Hh];        // double-buffered hidden state
__device__ float g_xw[Vv * Hh];          // token -> (emb@Wx + bx + bh)
__device__ int   g_bar8[8 * 32];         // per-row-group counters, 128B apart

static __device__ __forceinline__ float2 ffma2(float2 a, float2 b, float2 c) {
    union { float2 f; unsigned long long u; } A, B2, C;
    A.f = a; B2.f = b; C.f = c;
    asm("fma.rn.f32x2 %0, %1, %2, %0;" : "+l"(C.u) : "l"(A.u), "l"(B2.u));
    return C.f;
}

// one recursive-halving butterfly round over float2 array v[m] (V-path only)
#define BFLY2(v, m, s) {                                                  \
    const int  half_ = (m) >> 1;                                          \
    const bool up_ = (lane & (s)) != 0;                                   \
    _Pragma("unroll")                                                     \
    for (int i_ = 0; i_ < half_; ++i_) {                                  \
        float2 d_ = up_ ? v[i_] : v[i_ + half_];                          \
        float2 o_;                                                        \
        o_.x = __shfl_xor_sync(0xffffffffu, d_.x, (s));                   \
        o_.y = __shfl_xor_sync(0xffffffffu, d_.y, (s));                   \
        float2 k_ = up_ ? v[i_ + half_] : v[i_];                          \
        v[i_].x = k_.x + o_.x;                                            \
        v[i_].y = k_.y + o_.y;                                            \
    } }

__global__ void rnn_init_kernel() {
    int idx = blockIdx.x * blockDim.x + threadIdx.x;
    for (int i = idx; i < Bb * Hh; i += gridDim.x * blockDim.x)
        g_h[1][i] = 0.0f;                // h_{-1} = 0 (read at t=0)
    if (idx < 8 * 32) g_bar8[idx] = 0;
}

// g_xw[v][:] = emb[v] @ Wx + bx + bh   (tiny one-off GEMM, 128 blocks)
__global__ void __launch_bounds__(512) xw_kernel(
    const float* __restrict__ emb, const float* __restrict__ Wx,
    const float* __restrict__ bx,  const float* __restrict__ bh)
{
    __shared__ float se[Ee];
    const int v = blockIdx.x, j = threadIdx.x;
    if (j < Ee) se[j] = emb[v * Ee + j];
    __syncthreads();
    float acc = 0.f;
#pragma unroll 8
    for (int e = 0; e < Ee; ++e) acc = fmaf(se[e], Wx[e * Hh + j], acc);
    g_xw[v * Hh + j] = acc + bx[j] + bh[j];
}

__global__ void __launch_bounds__(NTHR, 1)
rnn_persistent(const int*   __restrict__ x,
               const float* __restrict__ Wh,
               const float* __restrict__ Wfc,
               const float* __restrict__ bfc,
               float* __restrict__ out)
{
    extern __shared__ float sm[];
    const int tid  = threadIdx.x;
    const int bidx = blockIdx.x;
    const int rgc  = bidx >> 4;          // row-group 0..7 (16 B-rows)
    const int R0   = rgc << 4;
    const int cg   = bidx & 15;
    const int C0   = cg << 5;            // 32 H-cols
    const int VC0  = cg << 3;            // 8 V-cols
    const int lane = tid & 31;
    const int ks   = lane;               // k-slice: k = m*128 + ks*4 + ki
    const int w    = tid >> 5;           // warp 0..7
    const int rowg = w >> 2;             // 0..1  -> rows rowg*8..+7
    const int colg = w & 3;              // 0..3  -> cols colg*8..+7
    const int hrow0 = rowg << 3;
    int* bar = &g_bar8[rgc * 32];
    // Wh swizzled unit positions for this lane (precomputed, loop-invariant)
    const int x0u = (colg * 2)     ^ (ks & 7);
    const int x1u = (colg * 2 + 1) ^ (ks & 7);
    // finalize mapping: thread -> h float2 (row i2, col j2)
    const int i2 = tid >> 4;             // 0..15
    const int j2 = (tid & 15) * 2;       // 0..30
    // V out-path butterfly row
    const int fr = lane >> 2;            // 0..7

    uint32_t smem_u32;
    asm("{ .reg .u64 t0; cvta.to.shared.u64 t0, %1; cvt.u32.u64 %0, t0; }"
        : "=r"(smem_u32) : "l"(sm));

    // ---- prologue: Wh slice (unit-XOR swizzle), Wfc slice --------------
    for (int idx = tid; idx < Hh * 32; idx += NTHR) {
        const int k = idx >> 5, c = idx & 31;
        const int unit = c >> 2, l = c & 3;
        const int u2 = unit ^ ((k >> 2) & 7);
        sm[OFF_WH + k * 32 + u2 * 4 + l] = Wh[k * Hh + C0 + c];
    }
    for (int idx = tid; idx < 8 * Hh; idx += NTHR) {
        const int c = idx >> 9, k = idx & 511;
        sm[OFF_WF + c * 512 + k] = Wfc[k * Vv + VC0 + c];
    }
    const float2 bfcv = *(const float2*)(bfc + VC0 + colg * 2);
    __syncthreads();

    const float4* wh4 = (const float4*)(sm + OFF_WH);

    for (int t = 0; t <= Ss; ++t) {
        // ---- per-warp acquire poll (domain: 16 CTAs x 8 warps = 128) ---
        if (t > 0) {
            if (lane == 0) {
                const int target = t << 7;
                int v;
                do {
                    asm volatile("ld.acquire.gpu.global.b32 %0, [%1];"
                                 : "=r"(v) : "l"(bar) : "memory");
                } while (v - target < 0);
            }
            __syncwarp();
        }
        // ---- stage h(t-1): warp w stages rows 2w,2w+1; two k-halves ----
        const float* hsrc = g_h[(t + 1) & 1];
#pragma unroll
        for (int j = 0; j < 4; ++j) {            // half A: units 0..63
            const int idx = lane + (j << 5);
            const int row = 2 * w + (idx >> 6);
            const int u   = idx & 63;
            const uint32_t sa = smem_u32 +
                (uint32_t)((OFF_SH + (row << 9) + u * 4) * 4);
            asm volatile("cp.async.cg.shared.global [%0], [%1], 16;"
                :: "r"(sa), "l"(((const float4*)(hsrc + ((R0 + row) << 9))) + u));
        }
        asm volatile("cp.async.commit_group;");
#pragma unroll
        for (int j = 0; j < 4; ++j) {            // half B: units 64..127
            const int idx = lane + (j << 5);
            const int row = 2 * w + (idx >> 6);
            const int u   = 64 + (idx & 63);
            const uint32_t sa = smem_u32 +
                (uint32_t)((OFF_SH + (row << 9) + u * 4) * 4);
            asm volatile("cp.async.cg.shared.global [%0], [%1], 16;"
                :: "r"(sa), "l"(((const float4*)(hsrc + ((R0 + row) << 9))) + u));
        }
        asm volatile("cp.async.commit_group;");

        int tk = 0;
        if (t < Ss) tk = __ldg(x + (R0 + i2) * Ss + t);

        asm volatile("cp.async.wait_group 1;");  // half A ready
        __syncthreads();

        float2 accV[8];
#pragma unroll
        for (int r = 0; r < 8; ++r) accV[r] = make_float2(0.f, 0.f);
        float2 accR[32];
        float2 xa = make_float2(0.f, 0.f);

        if (t < Ss) {
            // prefetch xw[token] (consumed in reduce, latency hidden)
            xa = __ldg((const float2*)(g_xw + tk * Hh + C0 + j2));
#pragma unroll
            for (int p = 0; p < 32; ++p) accR[p] = make_float2(0.f, 0.f);
            // ---- compute m = 0,1 on k-half A ---------------------------
#pragma unroll
            for (int m = 0; m < 2; ++m) {
                const int ub = m * 32 + ks;
                float4 h4[8];
#pragma unroll
                for (int r = 0; r < 8; ++r)
                    h4[r] = *(const float4*)(sm + OFF_SH
                              + ((hrow0 + r) << 9) + ub * 4);
                const float4 wfa = *(const float4*)(sm + OFF_WF
                              + ((colg * 2 + 0) << 9) + ub * 4);
                const float4 wfb = *(const float4*)(sm + OFF_WF
                              + ((colg * 2 + 1) << 9) + ub * 4);
#pragma unroll
                for (int ki = 0; ki < 4; ++ki) {
                    const int k = m * 128 + ks * 4 + ki;
                    const float4 wa = wh4[k * 8 + x0u];
                    const float4 wb = wh4[k * 8 + x1u];
                    const float2 wv = make_float2(((const float*)&wfa)[ki],
                                                  ((const float*)&wfb)[ki]);
#pragma unroll
                    for (int r = 0; r < 8; ++r) {
                        const float hv = ((const float*)&h4[r])[ki];
                        const float2 hh = make_float2(hv, hv);
                        accR[r*4+0] = ffma2(hh, make_float2(wa.x, wa.y), accR[r*4+0]);
                        accR[r*4+1] = ffma2(hh, make_float2(wa.z, wa.w), accR[r*4+1]);
                        accR[r*4+2] = ffma2(hh, make_float2(wb.x, wb.y), accR[r*4+2]);
                        accR[r*4+3] = ffma2(hh, make_float2(wb.z, wb.w), accR[r*4+3]);
                        accV[r]     = ffma2(hh, wv, accV[r]);
                    }
                }
            }
        }

        asm volatile("cp.async.wait_group 0;");  // half B ready
        __syncthreads();

        if (t < Ss) {
            // ---- compute m = 2,3 on k-half B ---------------------------
#pragma unroll
            for (int m = 2; m < 4; ++m) {
                const int ub = m * 32 + ks;
                float4 h4[8];
#pragma unroll
                for (int r = 0; r < 8; ++r)
                    h4[r] = *(const float4*)(sm + OFF_SH
                              + ((hrow0 + r) << 9) + ub * 4);
                const float4 wfa = *(const float4*)(sm + OFF_WF
                              + ((colg * 2 + 0) << 9) + ub * 4);
                const float4 wfb = *(const float4*)(sm + OFF_WF
                              + ((colg * 2 + 1) << 9) + ub * 4);
#pragma unroll
                for (int ki = 0; ki < 4; ++ki) {
                    const int k = m * 128 + ks * 4 + ki;
                    const float4 wa = wh4[k * 8 + x0u];
                    const float4 wb = wh4[k * 8 + x1u];
                    const float2 wv = make_float2(((const float*)&wfa)[ki],
                                                  ((const float*)&wfb)[ki]);
#pragma unroll
                    for (int r = 0; r < 8; ++r) {
                        const float hv = ((const float*)&h4[r])[ki];
                        const float2 hh = make_float2(hv, hv);
                        accR[r*4+0] = ffma2(hh, make_float2(wa.x, wa.y), accR[r*4+0]);
                        accR[r*4+1] = ffma2(hh, make_float2(wa.z, wa.w), accR[r*4+1]);
                        accR[r*4+2] = ffma2(hh, make_float2(wb.x, wb.y), accR[r*4+2]);
                        accR[r*4+3] = ffma2(hh, make_float2(wb.z, wb.w), accR[r*4+3]);
                        accV[r]     = ffma2(hh, wv, accV[r]);
                    }
                }
            }
            // ---- write rec partials -----------------------------------
#pragma unroll
            for (int r = 0; r < 8; ++r) {
                float* dst = sm + OFF_RR + ks * RR_STRIDE
                             + ((hrow0 + r) << 5) + colg * 8;
                *(float4*)dst       = make_float4(accR[r*4+0].x, accR[r*4+0].y,
                                                  accR[r*4+1].x, accR[r*4+1].y);
                *(float4*)(dst + 4) = make_float4(accR[r*4+2].x, accR[r*4+2].y,
                                                  accR[r*4+3].x, accR[r*4+3].y);
            }
            __syncthreads();
            // ---- reduce 32 slices, tanh, publish, per-warp release -----
            float2 s = xa;
#pragma unroll
            for (int sl = 0; sl < 32; ++sl) {
                const float2 v = *(const float2*)(sm + OFF_RR
                                    + sl * RR_STRIDE + tid * 2);
                s.x += v.x; s.y += v.y;
            }
            s.x = tanhf(s.x);
            s.y = tanhf(s.y);
            *(float2*)(&g_h[t & 1][((R0 + i2) << 9) + C0 + j2]) = s;
            __syncwarp();
            if (lane == 0)
                asm volatile("red.release.gpu.global.add.s32 [%0], %1;"
                             :: "l"(bar), "r"(1) : "memory");
        } else {
            // t == Ss: output projection of h(Ss-1) only
#pragma unroll
            for (int m = 0; m < 4; ++m) {
                const int ub = m * 32 + ks;
                const float4 wfa = *(const float4*)(sm + OFF_WF
                              + ((colg * 2 + 0) << 9) + ub * 4);
                const float4 wfb = *(const float4*)(sm + OFF_WF
                              + ((colg * 2 + 1) << 9) + ub * 4);
#pragma unroll
                for (int r = 0; r < 8; ++r) {
                    const float4 h4 = *(const float4*)(sm + OFF_SH
                              + ((hrow0 + r) << 9) + ub * 4);
#pragma unroll
                    for (int ki = 0; ki < 4; ++ki) {
                        const float hv = ((const float*)&h4)[ki];
                        const float2 wv = make_float2(((const float*)&wfa)[ki],
                                                      ((const float*)&wfb)[ki]);
                        accV[r] = ffma2(make_float2(hv, hv), wv, accV[r]);
                    }
                }
            }
        }

        // ---- out(t-1): in-warp V reduce, off inter-CTA critical path ---
        if (t > 0) {
            BFLY2(accV, 8, 16);
            BFLY2(accV, 4,  8);
            BFLY2(accV, 2,  4);
            accV[0].x += __shfl_xor_sync(0xffffffffu, accV[0].x, 2);
            accV[0].y += __shfl_xor_sync(0xffffffffu, accV[0].y, 2);
            accV[0].x += __shfl_xor_sync(0xffffffffu, accV[0].x, 1);
            accV[0].y += __shfl_xor_sync(0xffffffffu, accV[0].y, 1);
            if ((lane & 3) == 0) {
                float2 o = make_float2(accV[0].x + bfcv.x, accV[0].y + bfcv.y);
                *(float2*)(out + (long)(R0 + hrow0 + fr) * (Ss * Vv)
                           + (long)(t - 1) * Vv + VC0 + colg * 2) = o;
            }
        }
    }
}

extern "C" void kernel_launch(void* const* d_in, const int* in_sizes, int n_in,
                              void* d_out, int out_size) {
    const int*   x   = (const int*)  d_in[0];
    const float* emb = (const float*)d_in[1];
    const float* Wx  = (const float*)d_in[2];
    const float* bx  = (const float*)d_in[3];
    const float* Wh  = (const float*)d_in[4];
    const float* bh  = (const float*)d_in[5];
    const float* Wfc = (const float*)d_in[6];
    const float* bfc = (const float*)d_in[7];
    float* out = (float*)d_out;

    cudaFuncSetAttribute(rnn_persistent,
                         cudaFuncAttributeMaxDynamicSharedMemorySize, SMEM_BYTES);

    rnn_init_kernel<<<64, 256>>>();
    xw_kernel<<<Vv, 512>>>(emb, Wx, bx, bh);
    rnn_persistent<<<NBLK, NTHR, SMEM_BYTES>>>(x, Wh, Wfc, bfc, out);
}